// round 11
// baseline (speedup 1.0000x reference)
#include <cuda_runtime.h>
#include <math.h>

// ---------------- problem dims ----------------
#define TT        8192
#define INDIM     109
#define HDIM      1024
#define GDIM      4096           // 4*HDIM
#define NBLK      128            // LSTM blocks: 128 * 8 elems = 1024
#define EPB       8              // h-elements per block
#define NTHR      288            // 8 compute warps + 1 poller/stager warp

// ---------------- device scratch ----------------
__device__ float g_xp[TT * GDIM];                 // 128 MB: xp0 projections
__device__ float g_h1[TT * HDIM];                 // 32 MB layer-1 h history
// publish buffers: [parity][0..1023]=h0, [1024..2047]=h1 (float4-aligned)
__device__ __align__(16) float g_pubH[2][2048];
__device__ __align__(16) unsigned g_flag[NBLK];   // packed u32 flags (4 lines)

// ---------------- small helpers ----------------
__device__ __forceinline__ unsigned long long fma2(unsigned long long a,
                                                   unsigned long long b,
                                                   unsigned long long c) {
    unsigned long long d;
    asm("fma.rn.f32x2 %0, %1, %2, %3;" : "=l"(d) : "l"(a), "l"(b), "l"(c));
    return d;
}
__device__ __forceinline__ float2 unpack2(unsigned long long v) {
    float2 f;
    asm("mov.b64 {%0,%1}, %2;" : "=f"(f.x), "=f"(f.y) : "l"(v));
    return f;
}
__device__ __forceinline__ float fast_sigmoid(float x) {
    float e = __expf(-x);
    return __fdividef(1.f, 1.f + e);
}
__device__ __forceinline__ float fast_tanh(float x) {
    float e = __expf(-2.f * x);
    return fmaf(2.f, __fdividef(1.f, 1.f + e), -1.f);
}
__device__ __forceinline__ float warp_red4(float s) {
#pragma unroll
    for (int off = 16; off; off >>= 1)
        s += __shfl_xor_sync(0xffffffffu, s, off);
    return s;
}

__global__ void reset_state_kernel() {
    int i = threadIdx.x;                  // 1024 threads
    float* p = &g_pubH[0][0];             // 4096 floats total
#pragma unroll
    for (int q = 0; q < 4; q++) p[i + 1024 * q] = 0.f;
    if (i < NBLK) g_flag[i] = 0u;
}

// ---------------- xp0: [T,109] @ [4096,109]^T + bias ----------------
__global__ __launch_bounds__(256) void gemm_xproj_small(
    const float* __restrict__ A,      // [T][109]
    const float* __restrict__ B,      // [4096][109]
    const float* __restrict__ bias1,
    const float* __restrict__ bias2)
{
    __shared__ float sA[64][113];
    __shared__ float sB[32][113];
    int t0 = blockIdx.x * 64;
    int r0 = blockIdx.y * 32;
    int tid = threadIdx.x;
    int tx = tid & 15;
    int ty = tid >> 4;

    for (int idx = tid; idx < 64 * INDIM; idx += 256) {
        int row = idx / INDIM, k = idx - row * INDIM;
        sA[row][k] = A[(size_t)(t0 + row) * INDIM + k];
    }
    for (int idx = tid; idx < 32 * INDIM; idx += 256) {
        int row = idx / INDIM, k = idx - row * INDIM;
        sB[row][k] = B[(size_t)(r0 + row) * INDIM + k];
    }
    __syncthreads();

    float acc[4][2];
#pragma unroll
    for (int i = 0; i < 4; i++)
#pragma unroll
        for (int j = 0; j < 2; j++) acc[i][j] = 0.f;

    for (int k = 0; k < INDIM; k++) {
        float a[4], b[2];
#pragma unroll
        for (int i = 0; i < 4; i++) a[i] = sA[ty * 4 + i][k];
#pragma unroll
        for (int j = 0; j < 2; j++) b[j] = sB[tx * 2 + j][k];
#pragma unroll
        for (int i = 0; i < 4; i++)
#pragma unroll
            for (int j = 0; j < 2; j++) acc[i][j] = fmaf(a[i], b[j], acc[i][j]);
    }

#pragma unroll
    for (int j = 0; j < 2; j++) {
        int r = r0 + tx * 2 + j;
        float bs = __ldg(&bias1[r]) + __ldg(&bias2[r]);
#pragma unroll
        for (int i = 0; i < 4; i++) {
            int t = t0 + ty * 4 + i;
            g_xp[(size_t)t * GDIM + r] = acc[i][j] + bs;
        }
    }
}

// ---------------- fused 2-layer LSTM recurrence + poller warp -------------
// 128 blocks x 288 threads. Block b owns h0/h1 elems [8b, 8b+8).
// Compute warps 0..7: warp w owns element e = 8b+w of both layers.
// Warp 8 = poller/stager: issues xp loads, polls flags, stages h0/h1/xp into
// SMEM — all WHILE compute warps run the pre-poll wi matvec. Detect+stage
// leave the critical path.
// Step s computes h0_s (layer 0) and h1_{s-2} (layer 1):
//   compute pre-poll : a1 = W_ih1 @ h0_{s-2}  (reads sH0[(s+1)&1])
//   poller           : xp_s LDG; poll flags>=s; ldcg h -> sH0[s&1], sH1; STS xp
//   bar#1
//   compute post-poll: a0 = W_hh0(RF) @ h0_{s-1} (sH0[s&1]);
//                      a1 += W_hh1(SMEM+RF) @ h1_{s-3} (sH1);
//                      reduce; gates (xp from sXp); sPub
//   bar#2; tid0 publishes + releases; poller loops to poll s+1.
// SMEM: sWih1 131072 | sWhh1 81920 | sH0[2] 8192 | sH1 4096 | sPub 64 | sXp 128
#define FUS_SMEM (131072 + 81920 + 8192 + 4096 + 64 + 128)

__global__ __launch_bounds__(NTHR, 1) void lstm_fused_kernel(
    const float* __restrict__ Whh0,   // [4096][1024]
    const float* __restrict__ Wih1,   // [4096][1024]
    const float* __restrict__ Whh1,   // [4096][1024]
    const float* __restrict__ b_ih1,
    const float* __restrict__ b_hh1)
{
    extern __shared__ char smem[];
    float4* sWih1 = (float4*)(smem);                            // 32 rows x 256 f4
    float4* sWhh1 = (float4*)(smem + 131072);                   // 32 rows x 160 f4
    float4* sH0b  = (float4*)(smem + 131072 + 81920);           // [2][256] f4
    float4* sH1   = (float4*)(smem + 131072 + 81920 + 8192);    // 256 f4
    float*  sPub  = (float*)(smem + 131072 + 81920 + 12288);    // 16 floats
    float*  sXp   = (float*)(smem + 131072 + 81920 + 12288 + 64); // 32 floats

    int b   = blockIdx.x;
    int tid = threadIdx.x;
    int w   = tid >> 5;
    int l   = tid & 31;
    int e   = (b << 3) + (w & 7);

    // ---- RF weights (compute warps only; poller path stays light) ----
    ulonglong2 W0[4][8];              // W_hh0, full rows
    ulonglong2 W1r[4][3];             // W_hh1, k=5..7 (cols 640..1023)
    float bs1[4];
    if (w < 8) {
#pragma unroll
        for (int g = 0; g < 4; g++) {
            const ulonglong2* r0p =
                (const ulonglong2*)(Whh0 + (size_t)((g << 10) + e) * HDIM);
            const ulonglong2* r1p =
                (const ulonglong2*)(Whh1 + (size_t)((g << 10) + e) * HDIM);
#pragma unroll
            for (int k = 0; k < 8; k++) W0[g][k] = r0p[l + 32 * k];
#pragma unroll
            for (int k = 0; k < 3; k++) W1r[g][k] = r1p[l + 32 * (5 + k)];
        }
        if (l == 0) {
#pragma unroll
            for (int g = 0; g < 4; g++) {
                int r = (g << 10) + e;
                bs1[g] = __ldg(&b_ih1[r]) + __ldg(&b_hh1[r]);
            }
        }
    }

    // ---- SMEM weights (cooperative, all 288 threads) ----
    for (int idx = tid; idx < 32 * 256; idx += NTHR) {
        int rl = idx >> 8, c4 = idx & 255;
        int g = rl >> 3, ww = rl & 7;
        sWih1[idx] = ((const float4*)(Wih1 +
            (size_t)((g << 10) + (b << 3) + ww) * HDIM))[c4];
    }
    for (int idx = tid; idx < 32 * 160; idx += NTHR) {
        int rl = idx / 160, c4 = idx - rl * 160;
        int g = rl >> 3, ww = rl & 7;
        sWhh1[idx] = ((const float4*)(Whh1 +
            (size_t)((g << 10) + (b << 3) + ww) * HDIM))[c4];
    }

    // init SMEM h buffers + staging to zero
    if (tid < 256) {
        sH0b[tid] = make_float4(0.f, 0.f, 0.f, 0.f);
        sH0b[256 + tid] = make_float4(0.f, 0.f, 0.f, 0.f);
        sH1[tid] = make_float4(0.f, 0.f, 0.f, 0.f);
    }
    if (tid < 16) sPub[tid] = 0.f;
    if (tid < 32) sXp[tid] = 0.f;
    float c0 = 0.f, c1 = 0.f;
    __syncthreads();

    const uint4* flags4 = (const uint4*)g_flag;

    for (int s = 0; s <= TT + 1; s++) {
        if (w == 8) {
            // ================= POLLER / STAGER warp =================
            // xp load for step s (issued before poll -> DRAM latency hidden)
            float xv = 0.f;
            if (s < TT) {
                // lane l: gate = l>>3, elem = l&7
                xv = __ldg(g_xp + (size_t)s * GDIM + ((l >> 3) << 10)
                           + (b << 3) + (l & 7));
            }
            // poll all 128 flags (R5 barrier, warp-wide)
            if (s) {
                unsigned need = (unsigned)s;
                bool ok;
                do {
                    uint4 v;
                    asm volatile(
                        "ld.acquire.gpu.global.v4.u32 {%0,%1,%2,%3}, [%4];"
                        : "=r"(v.x), "=r"(v.y), "=r"(v.z), "=r"(v.w)
                        : "l"(flags4 + l) : "memory");
                    ok = v.x >= need && v.y >= need && v.z >= need && v.w >= need;
                } while (!__all_sync(0xffffffffu, ok));
            }
            // stage h0_{s-1} -> sH0[s&1], h1_{s-3} -> sH1 (512 f4 / 32 lanes)
            {
                const float4* pub4 = (const float4*)g_pubH[s & 1];
                float4 t0[8], t1[8];
#pragma unroll
                for (int i = 0; i < 8; i++) t0[i] = __ldcg(pub4 + 32 * i + l);
#pragma unroll
                for (int i = 0; i < 8; i++) t1[i] = __ldcg(pub4 + 256 + 32 * i + l);
                float4* dstH0 = sH0b + ((s & 1) << 8);
#pragma unroll
                for (int i = 0; i < 8; i++) dstH0[32 * i + l] = t0[i];
#pragma unroll
                for (int i = 0; i < 8; i++) sH1[32 * i + l] = t1[i];
            }
            sXp[l] = xv;
            __syncthreads();          // bar#1: stage ready
            __syncthreads();          // bar#2: step done
        } else {
            // ================= COMPUTE warps 0..7 =================
            const ulonglong2* H0pre =
                (const ulonglong2*)(sH0b + (((s + 1) & 1) << 8));
            const ulonglong2* wi = (const ulonglong2*)sWih1;

            // pre-poll: a1 = W_ih1 @ h0_{s-2}
            unsigned long long a1[4][2];
#pragma unroll
            for (int g = 0; g < 4; g++) { a1[g][0] = 0ull; a1[g][1] = 0ull; }
#pragma unroll
            for (int k = 0; k < 8; k++) {
                ulonglong2 hv = H0pre[32 * k + l];
#pragma unroll
                for (int g = 0; g < 4; g++) {
                    ulonglong2 wv = wi[(size_t)((g << 3) + w) * 256 + 32 * k + l];
                    a1[g][0] = fma2(wv.x, hv.x, a1[g][0]);
                    a1[g][1] = fma2(wv.y, hv.y, a1[g][1]);
                }
            }
            __syncthreads();          // bar#1: stage ready

            // post-poll: a0 = W_hh0 @ h0_{s-1}; a1 += W_hh1 @ h1_{s-3}
            const ulonglong2* H0c =
                (const ulonglong2*)(sH0b + ((s & 1) << 8));
            const ulonglong2* H1 = (const ulonglong2*)sH1;
            const ulonglong2* wh = (const ulonglong2*)sWhh1;
            unsigned long long a0[4][2];
#pragma unroll
            for (int g = 0; g < 4; g++) { a0[g][0] = 0ull; a0[g][1] = 0ull; }
#pragma unroll
            for (int k = 0; k < 8; k++) {
                ulonglong2 h0v = H0c[32 * k + l];
                ulonglong2 h1v = H1[32 * k + l];
#pragma unroll
                for (int g = 0; g < 4; g++) {
                    a0[g][0] = fma2(W0[g][k].x, h0v.x, a0[g][0]);
                    a0[g][1] = fma2(W0[g][k].y, h0v.y, a0[g][1]);
                    ulonglong2 wv1 = (k < 5)
                        ? wh[(size_t)((g << 3) + w) * 160 + 32 * k + l]
                        : W1r[g][k - 5];
                    a1[g][0] = fma2(wv1.x, h1v.x, a1[g][0]);
                    a1[g][1] = fma2(wv1.y, h1v.y, a1[g][1]);
                }
            }

            float dot0[4], dot1[4];
#pragma unroll
            for (int g = 0; g < 4; g++) {
                float2 lo0 = unpack2(a0[g][0]);
                float2 hi0 = unpack2(a0[g][1]);
                dot0[g] = warp_red4((lo0.x + lo0.y) + (hi0.x + hi0.y));
                float2 lo1 = unpack2(a1[g][0]);
                float2 hi1 = unpack2(a1[g][1]);
                dot1[g] = warp_red4((lo1.x + lo1.y) + (hi1.x + hi1.y));
            }

            // gates (lane 0)
            float h1n = 0.f;
            if (l == 0) {
                if (s < TT) {                     // layer 0: h0_s
                    float gi = dot0[0] + sXp[w];
                    float gf = dot0[1] + sXp[8 + w];
                    float gg = dot0[2] + sXp[16 + w];
                    float go = dot0[3] + sXp[24 + w];
                    float si = fast_sigmoid(gi);
                    float sf = fast_sigmoid(gf);
                    float so = fast_sigmoid(go);
                    float tg = fast_tanh(gg);
                    c0 = fmaf(sf, c0, si * tg);
                    sPub[w] = so * fast_tanh(c0);
                }
                if (s >= 2) {                     // layer 1: h1_{s-2}
                    float gi = dot1[0] + bs1[0];
                    float gf = dot1[1] + bs1[1];
                    float gg = dot1[2] + bs1[2];
                    float go = dot1[3] + bs1[3];
                    float si = fast_sigmoid(gi);
                    float sf = fast_sigmoid(gf);
                    float so = fast_sigmoid(go);
                    float tg = fast_tanh(gg);
                    c1 = fmaf(sf, c1, si * tg);
                    h1n = so * fast_tanh(c1);
                    sPub[8 + w] = h1n;
                }
            }
            __syncthreads();          // bar#2: sPub complete

            // publish (tid 0 only -> release covers its own stores)
            if (tid == 0) {
                float4 p0 = *(const float4*)&sPub[0];
                float4 p1 = *(const float4*)&sPub[4];
                float4 q0 = *(const float4*)&sPub[8];
                float4 q1 = *(const float4*)&sPub[12];
                float4* dst = (float4*)g_pubH[(s + 1) & 1];
                __stcg(dst + 2 * b,           p0);
                __stcg(dst + 2 * b + 1,       p1);
                __stcg(dst + 256 + 2 * b,     q0);
                __stcg(dst + 256 + 2 * b + 1, q1);
                asm volatile("st.release.gpu.global.u32 [%0], %1;"
                             :: "l"(&g_flag[b]), "r"((unsigned)(s + 1)) : "memory");
            }

            // h1 history (off the release path)
            if (l == 0 && s >= 2) {
                __stcg(&g_h1[(size_t)(s - 2) * HDIM + e], h1n);
            }
        }
    }
}

// ---------------- FC + log_softmax ----------------
__global__ __launch_bounds__(128) void fc_logsoftmax_kernel(
    const float* __restrict__ fcw,    // [109][1024]
    const float* __restrict__ fcb,    // [109]
    float* __restrict__ out)          // [T][109]
{
    __shared__ float sH[8 * 1024];
    __shared__ float sL[8][112];
    __shared__ float sLse[8];
    int t0 = blockIdx.x * 8;
    int tid = threadIdx.x;

    const float4* hg = (const float4*)(g_h1 + (size_t)t0 * HDIM);
    float4* sH4 = (float4*)sH;
#pragma unroll
    for (int q = 0; q < 16; q++) sH4[tid + 128 * q] = __ldg(hg + tid + 128 * q);
    __syncthreads();

    if (tid < INDIM) {
        float acc[8];
#pragma unroll
        for (int i = 0; i < 8; i++) acc[i] = 0.f;
        const float4* w4 = (const float4*)(fcw + (size_t)tid * HDIM);
        for (int k4 = 0; k4 < 256; k4++) {
            float4 w = __ldg(w4 + k4);
#pragma unroll
            for (int tt = 0; tt < 8; tt++) {
                float4 hv = sH4[tt * 256 + k4];
                acc[tt] = fmaf(w.x, hv.x,
                          fmaf(w.y, hv.y,
                          fmaf(w.z, hv.z,
                          fmaf(w.w, hv.w, acc[tt]))));
            }
        }
        float bb = __ldg(&fcb[tid]);
#pragma unroll
        for (int tt = 0; tt < 8; tt++) sL[tt][tid] = acc[tt] + bb;
    }
    __syncthreads();

    if (tid < 8) {
        float m = -1e30f;
        for (int n = 0; n < INDIM; n++) m = fmaxf(m, sL[tid][n]);
        float s = 0.f;
        for (int n = 0; n < INDIM; n++) s += expf(sL[tid][n] - m);
        sLse[tid] = m + logf(s);
    }
    __syncthreads();

    for (int idx = tid; idx < 8 * INDIM; idx += 128) {
        int tt = idx / INDIM, n = idx - tt * INDIM;
        out[(size_t)(t0 + tt) * INDIM + n] = sL[tt][n] - sLse[tt];
    }
}

// ---------------- launcher ----------------
extern "C" void kernel_launch(void* const* d_in, const int* in_sizes, int n_in,
                              void* d_out, int out_size) {
    const float* input = (const float*)d_in[0];
    const float* W_ih0 = (const float*)d_in[1];
    const float* W_hh0 = (const float*)d_in[2];
    const float* b_ih0 = (const float*)d_in[3];
    const float* b_hh0 = (const float*)d_in[4];
    const float* W_ih1 = (const float*)d_in[5];
    const float* W_hh1 = (const float*)d_in[6];
    const float* b_ih1 = (const float*)d_in[7];
    const float* b_hh1 = (const float*)d_in[8];
    const float* fc_w  = (const float*)d_in[9];
    const float* fc_b  = (const float*)d_in[10];
    float* out = (float*)d_out;

    cudaFuncSetAttribute(lstm_fused_kernel,
                         cudaFuncAttributeMaxDynamicSharedMemorySize, FUS_SMEM);

    // xp0 = input @ W_ih0^T + b_ih0 + b_hh0
    gemm_xproj_small<<<dim3(TT / 64, GDIM / 32), 256>>>(input, W_ih0, b_ih0, b_hh0);

    // fused 2-layer recurrence -> g_h1
    reset_state_kernel<<<1, 1024>>>();
    lstm_fused_kernel<<<NBLK, NTHR, FUS_SMEM>>>(W_hh0, W_ih1, W_hh1, b_ih1, b_hh1);

    // logits + log_softmax
    fc_logsoftmax_kernel<<<TT / 8, 128>>>(fc_w, fc_b, out);
}

// round 12
// speedup vs baseline: 3.3203x; 3.3203x over previous
#include <cuda_runtime.h>
#include <math.h>

// ---------------- problem dims ----------------
#define TT        8192
#define INDIM     109
#define HDIM      1024
#define GDIM      4096           // 4*HDIM
#define NBLK      128            // LSTM blocks: 128 * 8 elems = 1024
#define EPB       8              // h-elements per block

// ---------------- device scratch ----------------
__device__ float g_xp[TT * GDIM];                 // 128 MB: xp0 projections
__device__ float g_h1[TT * HDIM];                 // 32 MB layer-1 h history
// publish buffers: [parity][0..1023]=h0, [1024..2047]=h1 (float4-aligned)
__device__ __align__(16) float g_pubH[2][2048];
__device__ __align__(16) unsigned g_flag[NBLK];   // packed u32 flags (4 lines)

// ---------------- small helpers ----------------
__device__ __forceinline__ unsigned long long fma2(unsigned long long a,
                                                   unsigned long long b,
                                                   unsigned long long c) {
    unsigned long long d;
    asm("fma.rn.f32x2 %0, %1, %2, %3;" : "=l"(d) : "l"(a), "l"(b), "l"(c));
    return d;
}
__device__ __forceinline__ float2 unpack2(unsigned long long v) {
    float2 f;
    asm("mov.b64 {%0,%1}, %2;" : "=f"(f.x), "=f"(f.y) : "l"(v));
    return f;
}
__device__ __forceinline__ float fast_tanh(float x) {
    float e = __expf(-2.f * x);
    return fmaf(2.f, __fdividef(1.f, 1.f + e), -1.f);
}
__device__ __forceinline__ float warp_red4(float s) {
#pragma unroll
    for (int off = 16; off; off >>= 1)
        s += __shfl_xor_sync(0xffffffffu, s, off);
    return s;
}

__global__ void reset_state_kernel() {
    int i = threadIdx.x;                  // 1024 threads
    float* p = &g_pubH[0][0];             // 4096 floats total
#pragma unroll
    for (int q = 0; q < 4; q++) p[i + 1024 * q] = 0.f;
    if (i < NBLK) g_flag[i] = 0u;
}

// ---------------- xp0: [T,109] @ [4096,109]^T + bias ----------------
__global__ __launch_bounds__(256) void gemm_xproj_small(
    const float* __restrict__ A,      // [T][109]
    const float* __restrict__ B,      // [4096][109]
    const float* __restrict__ bias1,
    const float* __restrict__ bias2)
{
    __shared__ float sA[64][113];
    __shared__ float sB[32][113];
    int t0 = blockIdx.x * 64;
    int r0 = blockIdx.y * 32;
    int tid = threadIdx.x;
    int tx = tid & 15;
    int ty = tid >> 4;

    for (int idx = tid; idx < 64 * INDIM; idx += 256) {
        int row = idx / INDIM, k = idx - row * INDIM;
        sA[row][k] = A[(size_t)(t0 + row) * INDIM + k];
    }
    for (int idx = tid; idx < 32 * INDIM; idx += 256) {
        int row = idx / INDIM, k = idx - row * INDIM;
        sB[row][k] = B[(size_t)(r0 + row) * INDIM + k];
    }
    __syncthreads();

    float acc[4][2];
#pragma unroll
    for (int i = 0; i < 4; i++)
#pragma unroll
        for (int j = 0; j < 2; j++) acc[i][j] = 0.f;

    for (int k = 0; k < INDIM; k++) {
        float a[4], b[2];
#pragma unroll
        for (int i = 0; i < 4; i++) a[i] = sA[ty * 4 + i][k];
#pragma unroll
        for (int j = 0; j < 2; j++) b[j] = sB[tx * 2 + j][k];
#pragma unroll
        for (int i = 0; i < 4; i++)
#pragma unroll
            for (int j = 0; j < 2; j++) acc[i][j] = fmaf(a[i], b[j], acc[i][j]);
    }

#pragma unroll
    for (int j = 0; j < 2; j++) {
        int r = r0 + tx * 2 + j;
        float bs = __ldg(&bias1[r]) + __ldg(&bias2[r]);
#pragma unroll
        for (int i = 0; i < 4; i++) {
            int t = t0 + ty * 4 + i;
            g_xp[(size_t)t * GDIM + r] = acc[i][j] + bs;
        }
    }
}

// ---------------- fused 2-layer LSTM recurrence (R10 + parallel gates) -----
// 128 blocks x 256 threads. Block b owns h0/h1 elems [8b, 8b+8).
// Warp w owns element e = 8b+w of both layers.
// Step s computes h0_s (layer 0) and h1_{s-2} (layer 1):
//   pre-poll  : a1 = W_ih1 @ h0_{s-2}   (staged at step s-1)
//   poll      : R5 barrier — warp 0, one ld.acquire.v4 per lane, 4 lines
//   stage     : h0_{s-1}, h1_{s-3} -> SMEM (ldcg, parity s&1)
//   post-poll : a0 = W_hh0(RF) @ h0_{s-1}; a1 += W_hh1(SMEM+RF) @ h1_{s-3};
//               reduce (all lanes get totals); PARALLEL activations on lanes
//               0-7 (selp, no divergence); quad shfl; c0 on lane 0, c1 on
//               lane 4; publish; release.
// xp loads: lane g in 0..3 loads its own gate's xp. Bias: lanes 4-7.
// SMEM: sWih1 131072 | sWhh1 81920 | sH0 4096 | sH1 4096 | sPub 64
#define FUS_SMEM (131072 + 81920 + 4096 + 4096 + 64)

__global__ __launch_bounds__(256, 1) void lstm_fused_kernel(
    const float* __restrict__ Whh0,   // [4096][1024]
    const float* __restrict__ Wih1,   // [4096][1024]
    const float* __restrict__ Whh1,   // [4096][1024]
    const float* __restrict__ b_ih1,
    const float* __restrict__ b_hh1)
{
    extern __shared__ char smem[];
    float4* sWih1 = (float4*)(smem);                            // 32 rows x 256 f4
    float4* sWhh1 = (float4*)(smem + 131072);                   // 32 rows x 160 f4
    float4* sH0   = (float4*)(smem + 131072 + 81920);           // 256 f4
    float4* sH1   = (float4*)(smem + 131072 + 81920 + 4096);    // 256 f4
    float*  sPub  = (float*)(smem + 131072 + 81920 + 8192);     // 16 floats

    int b   = blockIdx.x;
    int tid = threadIdx.x;
    int w   = tid >> 5;
    int l   = tid & 31;
    int e   = (b << 3) + w;
    int gl  = l & 3;                  // gate index for lanes 0..7

    // ---- RF weights ----
    ulonglong2 W0[4][8];              // W_hh0, full rows
    ulonglong2 W1r[4][3];             // W_hh1, k=5..7 (cols 640..1023)
#pragma unroll
    for (int g = 0; g < 4; g++) {
        const ulonglong2* r0p =
            (const ulonglong2*)(Whh0 + (size_t)((g << 10) + e) * HDIM);
        const ulonglong2* r1p =
            (const ulonglong2*)(Whh1 + (size_t)((g << 10) + e) * HDIM);
#pragma unroll
        for (int k = 0; k < 8; k++) W0[g][k] = r0p[l + 32 * k];
#pragma unroll
        for (int k = 0; k < 3; k++) W1r[g][k] = r1p[l + 32 * (5 + k)];
    }

    // ---- SMEM weights (cooperative) ----
    for (int idx = tid; idx < 32 * 256; idx += 256) {
        int rl = idx >> 8, c4 = idx & 255;
        int g = rl >> 3, ww = rl & 7;
        sWih1[idx] = ((const float4*)(Wih1 +
            (size_t)((g << 10) + (b << 3) + ww) * HDIM))[c4];
    }
    for (int idx = tid; idx < 32 * 160; idx += 256) {
        int rl = idx / 160, c4 = idx - rl * 160;
        int g = rl >> 3, ww = rl & 7;
        sWhh1[idx] = ((const float4*)(Whh1 +
            (size_t)((g << 10) + (b << 3) + ww) * HDIM))[c4];
    }

    // layer-1 bias sum on lanes 4..7 (lane 4+g holds gate g's bias)
    float bs1v = 0.f;
    if (l >= 4 && l < 8) {
        int r = (gl << 10) + e;
        bs1v = __ldg(&b_ih1[r]) + __ldg(&b_hh1[r]);
    }

    // init SMEM h buffers + pub staging to zero
    sH0[tid] = make_float4(0.f, 0.f, 0.f, 0.f);
    sH1[tid] = make_float4(0.f, 0.f, 0.f, 0.f);
    if (tid < 16) sPub[tid] = 0.f;
    float c0 = 0.f, c1 = 0.f;         // c0 on lane 0, c1 on lane 4
    __syncthreads();

    const uint4* flags4 = (const uint4*)g_flag;

    // prefetch xp0 for s=0: lane g in 0..3 loads gate g
    float xv = 0.f;
    if (l < 4) xv = __ldg(g_xp + (gl << 10) + e);

    const ulonglong2* H0 = (const ulonglong2*)sH0;
    const ulonglong2* H1 = (const ulonglong2*)sH1;
    const ulonglong2* wi = (const ulonglong2*)sWih1;
    const ulonglong2* wh = (const ulonglong2*)sWhh1;

    for (int s = 0; s <= TT + 1; s++) {
        // ===== pre-poll: W_ih1 @ h0_{s-2} (staged at step s-1) =====
        unsigned long long a1[4][2];
#pragma unroll
        for (int g = 0; g < 4; g++) { a1[g][0] = 0ull; a1[g][1] = 0ull; }
#pragma unroll
        for (int k = 0; k < 8; k++) {
            ulonglong2 hv = H0[32 * k + l];
#pragma unroll
            for (int g = 0; g < 4; g++) {
                ulonglong2 wv = wi[(size_t)((g << 3) + w) * 256 + 32 * k + l];
                a1[g][0] = fma2(wv.x, hv.x, a1[g][0]);
                a1[g][1] = fma2(wv.y, hv.y, a1[g][1]);
            }
        }

        // prefetch xp0 for next step (consumed one step later)
        float nxv = 0.f;
        if (l < 4 && s + 1 < TT)
            nxv = __ldg(g_xp + (size_t)(s + 1) * GDIM + (gl << 10) + e);

        // ===== poll (R5 barrier, byte-for-byte) =====
        if (s) {
            if (w == 0) {
                unsigned need = (unsigned)s;
                bool ok;
                do {
                    uint4 v;
                    asm volatile(
                        "ld.acquire.gpu.global.v4.u32 {%0,%1,%2,%3}, [%4];"
                        : "=r"(v.x), "=r"(v.y), "=r"(v.z), "=r"(v.w)
                        : "l"(flags4 + l) : "memory");
                    ok = v.x >= need && v.y >= need && v.z >= need && v.w >= need;
                } while (!__all_sync(0xffffffffu, ok));
            }
        }
        __syncthreads();   // also separates pre-poll reads of sH0 from restage

        // ===== stage h0_{s-1}, h1_{s-3} =====
        {
            const float4* pub4 = (const float4*)g_pubH[s & 1];
            sH0[tid] = __ldcg(pub4 + tid);
            sH1[tid] = __ldcg(pub4 + 256 + tid);
        }
        __syncthreads();

        // ===== post-poll: W_hh0 @ h0_{s-1}  and  a1 += W_hh1 @ h1_{s-3} =====
        unsigned long long a0[4][2];
#pragma unroll
        for (int g = 0; g < 4; g++) { a0[g][0] = 0ull; a0[g][1] = 0ull; }
#pragma unroll
        for (int k = 0; k < 8; k++) {
            ulonglong2 h0v = H0[32 * k + l];
            ulonglong2 h1v = H1[32 * k + l];
#pragma unroll
            for (int g = 0; g < 4; g++) {
                a0[g][0] = fma2(W0[g][k].x, h0v.x, a0[g][0]);
                a0[g][1] = fma2(W0[g][k].y, h0v.y, a0[g][1]);
                ulonglong2 wv1 = (k < 5)
                    ? wh[(size_t)((g << 3) + w) * 160 + 32 * k + l]
                    : W1r[g][k - 5];
                a1[g][0] = fma2(wv1.x, h1v.x, a1[g][0]);
                a1[g][1] = fma2(wv1.y, h1v.y, a1[g][1]);
            }
        }

        // xor-shuffle reduce: EVERY lane ends with the full dot products
        float dot0[4], dot1[4];
#pragma unroll
        for (int g = 0; g < 4; g++) {
            float2 lo0 = unpack2(a0[g][0]);
            float2 hi0 = unpack2(a0[g][1]);
            dot0[g] = warp_red4((lo0.x + lo0.y) + (hi0.x + hi0.y));
            float2 lo1 = unpack2(a1[g][0]);
            float2 hi1 = unpack2(a1[g][1]);
            dot1[g] = warp_red4((lo1.x + lo1.y) + (hi1.x + hi1.y));
        }

        // ===== parallel gate activations (lanes 0..7, branch-free) =====
        // lanes 0-3: layer-0 gate gl; lanes 4-7: layer-1 gate gl.
        float pre = ((l & 4) ? dot1[gl] + bs1v : dot0[gl] + xv);
        float kx  = (gl == 2) ? 2.f * pre : pre;        // tanh needs 2x
        float ev  = __expf(-kx);
        float rv  = __fdividef(1.f, 1.f + ev);
        float act = (gl == 2) ? fmaf(2.f, rv, -1.f) : rv;

        // gather this layer's quad (base = 0 for lanes<4-group, 4 otherwise)
        int base = l & 4;
        float iv = __shfl_sync(0xffffffffu, act, base + 0);
        float fv = __shfl_sync(0xffffffffu, act, base + 1);
        float gv = __shfl_sync(0xffffffffu, act, base + 2);
        float ov = __shfl_sync(0xffffffffu, act, base + 3);

        float h1n = 0.f;
        if (l == 0 && s < TT) {                   // layer 0: h0_s
            c0 = fmaf(fv, c0, iv * gv);
            sPub[w] = ov * fast_tanh(c0);
        }
        if (l == 4 && s >= 2) {                   // layer 1: h1_{s-2}
            c1 = fmaf(fv, c1, iv * gv);
            h1n = ov * fast_tanh(c1);
            sPub[8 + w] = h1n;
        }
        __syncthreads();

        // ===== publish (tid 0 only -> release covers its own stores) =====
        if (tid == 0) {
            float4 p0 = *(const float4*)&sPub[0];
            float4 p1 = *(const float4*)&sPub[4];
            float4 q0 = *(const float4*)&sPub[8];
            float4 q1 = *(const float4*)&sPub[12];
            float4* dst = (float4*)g_pubH[(s + 1) & 1];
            __stcg(dst + 2 * b,           p0);
            __stcg(dst + 2 * b + 1,       p1);
            __stcg(dst + 256 + 2 * b,     q0);
            __stcg(dst + 256 + 2 * b + 1, q1);
            asm volatile("st.release.gpu.global.u32 [%0], %1;"
                         :: "l"(&g_flag[b]), "r"((unsigned)(s + 1)) : "memory");
        }

        // ===== h1 history (off the release path, lane 4) =====
        if (l == 4 && s >= 2) {
            __stcg(&g_h1[(size_t)(s - 2) * HDIM + e], h1n);
        }

        xv = nxv;
    }
}

// ---------------- FC + log_softmax ----------------
__global__ __launch_bounds__(128) void fc_logsoftmax_kernel(
    const float* __restrict__ fcw,    // [109][1024]
    const float* __restrict__ fcb,    // [109]
    float* __restrict__ out)          // [T][109]
{
    __shared__ float sH[8 * 1024];
    __shared__ float sL[8][112];
    __shared__ float sLse[8];
    int t0 = blockIdx.x * 8;
    int tid = threadIdx.x;

    const float4* hg = (const float4*)(g_h1 + (size_t)t0 * HDIM);
    float4* sH4 = (float4*)sH;
#pragma unroll
    for (int q = 0; q < 16; q++) sH4[tid + 128 * q] = __ldg(hg + tid + 128 * q);
    __syncthreads();

    if (tid < INDIM) {
        float acc[8];
#pragma unroll
        for (int i = 0; i < 8; i++) acc[i] = 0.f;
        const float4* w4 = (const float4*)(fcw + (size_t)tid * HDIM);
        for (int k4 = 0; k4 < 256; k4++) {
            float4 w = __ldg(w4 + k4);
#pragma unroll
            for (int tt = 0; tt < 8; tt++) {
                float4 hv = sH4[tt * 256 + k4];
                acc[tt] = fmaf(w.x, hv.x,
                          fmaf(w.y, hv.y,
                          fmaf(w.z, hv.z,
                          fmaf(w.w, hv.w, acc[tt]))));
            }
        }
        float bb = __ldg(&fcb[tid]);
#pragma unroll
        for (int tt = 0; tt < 8; tt++) sL[tt][tid] = acc[tt] + bb;
    }
    __syncthreads();

    if (tid < 8) {
        float m = -1e30f;
        for (int n = 0; n < INDIM; n++) m = fmaxf(m, sL[tid][n]);
        float s = 0.f;
        for (int n = 0; n < INDIM; n++) s += expf(sL[tid][n] - m);
        sLse[tid] = m + logf(s);
    }
    __syncthreads();

    for (int idx = tid; idx < 8 * INDIM; idx += 128) {
        int tt = idx / INDIM, n = idx - tt * INDIM;
        out[(size_t)(t0 + tt) * INDIM + n] = sL[tt][n] - sLse[tt];
    }
}

// ---------------- launcher ----------------
extern "C" void kernel_launch(void* const* d_in, const int* in_sizes, int n_in,
                              void* d_out, int out_size) {
    const float* input = (const float*)d_in[0];
    const float* W_ih0 = (const float*)d_in[1];
    const float* W_hh0 = (const float*)d_in[2];
    const float* b_ih0 = (const float*)d_in[3];
    const float* b_hh0 = (const float*)d_in[4];
    const float* W_ih1 = (const float*)d_in[5];
    const float* W_hh1 = (const float*)d_in[6];
    const float* b_ih1 = (const float*)d_in[7];
    const float* b_hh1 = (const float*)d_in[8];
    const float* fc_w  = (const float*)d_in[9];
    const float* fc_b  = (const float*)d_in[10];
    float* out = (float*)d_out;

    cudaFuncSetAttribute(lstm_fused_kernel,
                         cudaFuncAttributeMaxDynamicSharedMemorySize, FUS_SMEM);

    // xp0 = input @ W_ih0^T + b_ih0 + b_hh0
    gemm_xproj_small<<<dim3(TT / 64, GDIM / 32), 256>>>(input, W_ih0, b_ih0, b_hh0);

    // fused 2-layer recurrence -> g_h1
    reset_state_kernel<<<1, 1024>>>();
    lstm_fused_kernel<<<NBLK, 256, FUS_SMEM>>>(W_hh0, W_ih1, W_hh1, b_ih1, b_hh1);

    // logits + log_softmax
    fc_logsoftmax_kernel<<<TT / 8, 128>>>(fc_w, fc_b, out);
}